// round 6
// baseline (speedup 1.0000x reference)
#include <cuda_runtime.h>
#include <cstdint>

#define BB 2
#define LL 2048
#define DD 1024
#define HH 16
#define NEGV (-1000000000.0f)
#define EPSV 1e-6f

// ---------------- scratch (no allocations allowed) ----------------
__device__ float g_q4[(size_t)BB * LL * DD];       // Q proj, pre-scaled by 1/8
__device__ float g_k4[(size_t)BB * LL * DD];       // K proj
__device__ float g_vt[(size_t)BB * HH * 64 * LL];  // V proj transposed [b][h][d][l]
__device__ float g_ctx[(size_t)BB * LL * DD];      // ctx
__device__ float g_tmp[(size_t)BB * LL * DD];      // V natural, then pre-LN
__device__ float g_stat_m[(size_t)BB * HH * LL * 16];  // per (row, ktile) max
__device__ float g_stat_l[(size_t)BB * HH * LL * 16];  // per (row, ktile) sumexp

// ---------------- tf32 helpers ----------------
__device__ __forceinline__ uint32_t f2tf(float f) {
    uint32_t u;
    asm("cvt.rna.tf32.f32 %0, %1;" : "=r"(u) : "f"(f));
    return u;
}

__device__ __forceinline__ void mma8(float* c, const uint32_t* a, const uint32_t* b) {
    asm volatile(
        "mma.sync.aligned.m16n8k8.row.col.f32.tf32.tf32.f32 "
        "{%0,%1,%2,%3}, {%4,%5,%6,%7}, {%8,%9}, {%0,%1,%2,%3};"
        : "+f"(c[0]), "+f"(c[1]), "+f"(c[2]), "+f"(c[3])
        : "r"(a[0]), "r"(a[1]), "r"(a[2]), "r"(a[3]), "r"(b[0]), "r"(b[1]));
}

// =====================================================================
// NT GEMM core: C[128 x NROWS] += A[128 x K] * B[NROWS x K]^T
// 256 threads, 8 warps (4 M x 2 N), warp tile 32 x NROWS/2.
// BK=16, double-buffered smem, row pad to 20 floats.
// =====================================================================
template <int NROWS>
__device__ __forceinline__ void gemm_tc(const float* __restrict__ A, int lda,
                                        const float* __restrict__ B, int ldb,
                                        int K, float acc[2][NROWS / 16][4]) {
    constexpr int NT = NROWS / 16;
    constexpr int BT = NROWS / 64;
    __shared__ float As[2][128 * 20];
    __shared__ float Bs[2][NROWS * 20];

    const int tid = threadIdx.x;
    const int lane = tid & 31, w = tid >> 5;
    const int m_base = (w & 3) * 32;
    const int n_base = (w >> 2) * (NROWS / 2);
    const int gr = lane >> 2, tq = lane & 3;

#pragma unroll
    for (int i = 0; i < 2; i++)
#pragma unroll
        for (int j = 0; j < NT; j++)
#pragma unroll
            for (int r = 0; r < 4; r++) acc[i][j][r] = 0.f;

    const int S = K >> 4;
    float4 ra[2], rb[BT];

#pragma unroll
    for (int t = 0; t < 2; t++) {
        int idx = tid + t * 256;
        ra[t] = *(const float4*)(A + (size_t)(idx >> 2) * lda + ((idx & 3) << 2));
    }
#pragma unroll
    for (int t = 0; t < BT; t++) {
        int idx = tid + t * 256;
        rb[t] = *(const float4*)(B + (size_t)(idx >> 2) * ldb + ((idx & 3) << 2));
    }
#pragma unroll
    for (int t = 0; t < 2; t++) {
        int idx = tid + t * 256;
        *(float4*)&As[0][(idx >> 2) * 20 + ((idx & 3) << 2)] = ra[t];
    }
#pragma unroll
    for (int t = 0; t < BT; t++) {
        int idx = tid + t * 256;
        *(float4*)&Bs[0][(idx >> 2) * 20 + ((idx & 3) << 2)] = rb[t];
    }
    __syncthreads();

    for (int s = 0; s < S; s++) {
        const int cur = s & 1;
        if (s + 1 < S) {
            const int k0 = (s + 1) << 4;
#pragma unroll
            for (int t = 0; t < 2; t++) {
                int idx = tid + t * 256;
                ra[t] = *(const float4*)(A + (size_t)(idx >> 2) * lda + k0 + ((idx & 3) << 2));
            }
#pragma unroll
            for (int t = 0; t < BT; t++) {
                int idx = tid + t * 256;
                rb[t] = *(const float4*)(B + (size_t)(idx >> 2) * ldb + k0 + ((idx & 3) << 2));
            }
        }

#pragma unroll
        for (int kk = 0; kk < 16; kk += 8) {
            uint32_t af[2][4], bf[NT][2];
#pragma unroll
            for (int i = 0; i < 2; i++) {
                const float* ap = &As[cur][(m_base + i * 16) * 20 + kk];
                af[i][0] = f2tf(ap[gr * 20 + tq]);
                af[i][1] = f2tf(ap[(gr + 8) * 20 + tq]);
                af[i][2] = f2tf(ap[gr * 20 + tq + 4]);
                af[i][3] = f2tf(ap[(gr + 8) * 20 + tq + 4]);
            }
#pragma unroll
            for (int j = 0; j < NT; j++) {
                const float* bp = &Bs[cur][(n_base + j * 8 + gr) * 20 + kk + tq];
                bf[j][0] = f2tf(bp[0]);
                bf[j][1] = f2tf(bp[4]);
            }
#pragma unroll
            for (int i = 0; i < 2; i++)
#pragma unroll
                for (int j = 0; j < NT; j++) mma8(acc[i][j], af[i], bf[j]);
        }

        if (s + 1 < S) {
            const int nxt = cur ^ 1;
#pragma unroll
            for (int t = 0; t < 2; t++) {
                int idx = tid + t * 256;
                *(float4*)&As[nxt][(idx >> 2) * 20 + ((idx & 3) << 2)] = ra[t];
            }
#pragma unroll
            for (int t = 0; t < BT; t++) {
                int idx = tid + t * 256;
                *(float4*)&Bs[nxt][(idx >> 2) * 20 + ((idx & 3) << 2)] = rb[t];
            }
        }
        __syncthreads();
    }
}

// ---------------- projection: out = X @ W^T + b (times scale) ----------------
__global__ __launch_bounds__(256) void k_proj(const float* __restrict__ X,
                                              const float* __restrict__ W,
                                              const float* __restrict__ bias,
                                              float scale, int sel) {
    float acc[2][8][4];
    const float* A = X + (size_t)blockIdx.y * 128 * DD;
    const float* Bp = W + (size_t)blockIdx.x * 128 * DD;
    gemm_tc<128>(A, DD, Bp, DD, DD, acc);

    float* out = (sel == 0) ? g_q4 : (sel == 1) ? g_k4 : g_tmp;
    const int lane = threadIdx.x & 31, w = threadIdx.x >> 5;
    const int m0 = blockIdx.y * 128 + (w & 3) * 32;
    const int n0 = blockIdx.x * 128 + (w >> 2) * 64;
    const int gr = lane >> 2, tq = lane & 3;
#pragma unroll
    for (int i = 0; i < 2; i++) {
        const int r0 = m0 + i * 16 + gr;
#pragma unroll
        for (int j = 0; j < 8; j++) {
            const int col = n0 + j * 8 + tq * 2;
            const float b0 = bias[col], b1 = bias[col + 1];
            *(float2*)(out + (size_t)r0 * DD + col) =
                make_float2((acc[i][j][0] + b0) * scale, (acc[i][j][1] + b1) * scale);
            *(float2*)(out + (size_t)(r0 + 8) * DD + col) =
                make_float2((acc[i][j][2] + b0) * scale, (acc[i][j][3] + b1) * scale);
        }
    }
}

// ---------------- transpose V: g_tmp -> g_vt [b][h][d][l] ----------------
__global__ __launch_bounds__(256) void k_trans() {
    __shared__ float t[32][33];
    const int b = blockIdx.z >> 4, h = blockIdx.z & 15;
    const int l0 = blockIdx.x * 32, d0 = blockIdx.y * 32;
    for (int i = threadIdx.y; i < 32; i += 8)
        t[i][threadIdx.x] =
            g_tmp[(size_t)(b * LL + l0 + i) * DD + h * 64 + d0 + threadIdx.x];
    __syncthreads();
    for (int i = threadIdx.y; i < 32; i += 8)
        g_vt[((size_t)((b * HH + h) * 64) + d0 + i) * LL + l0 + threadIdx.x] =
            t[threadIdx.x][i];
}

// ---------------- scores + mask + per-tile softmax stats ----------------
__global__ __launch_bounds__(256) void k_score(float* __restrict__ attn,
                                               const int* __restrict__ mask) {
    float acc[2][8][4];
    const int z = blockIdx.z, b_ = z >> 4, h = z & 15;
    const float* A = g_q4 + (size_t)b_ * LL * DD + h * 64 + (size_t)blockIdx.y * 128 * DD;
    const float* Bp = g_k4 + (size_t)b_ * LL * DD + h * 64 + (size_t)blockIdx.x * 128 * DD;
    gemm_tc<128>(A, DD, Bp, DD, 64, acc);

    __shared__ float sm[2][128], sl[2][128];

    float* Cb = attn + (size_t)z * LL * LL;
    const int tid = threadIdx.x;
    const int lane = tid & 31, w = tid >> 5;
    const int wn = w >> 2;                    // n-half (0,1)
    const int mloc = (w & 3) * 32;            // warp row base (CTA-local)
    const int gm0 = blockIdx.y * 128;         // CTA global row base
    const int n0 = blockIdx.x * 128 + wn * 64;
    const int gr = lane >> 2, tq = lane & 3;

    // mask + store + per-thread row max (rows: mloc+i*16+gr, +8)
    float vmax[2][2] = {{-3.4e38f, -3.4e38f}, {-3.4e38f, -3.4e38f}};
#pragma unroll
    for (int i = 0; i < 2; i++) {
        const int rl = mloc + i * 16 + gr;          // CTA-local row (low)
        const size_t mrow0 = ((size_t)b_ * LL + gm0 + rl) * LL;
        const size_t mrow1 = ((size_t)b_ * LL + gm0 + rl + 8) * LL;
#pragma unroll
        for (int j = 0; j < 8; j++) {
            const int col = n0 + j * 8 + tq * 2;
            int2 k0 = *(const int2*)(mask + mrow0 + col);
            int2 k1 = *(const int2*)(mask + mrow1 + col);
            float v0 = (k0.x == 0) ? NEGV : acc[i][j][0];
            float v1 = (k0.y == 0) ? NEGV : acc[i][j][1];
            float v2 = (k1.x == 0) ? NEGV : acc[i][j][2];
            float v3 = (k1.y == 0) ? NEGV : acc[i][j][3];
            acc[i][j][0] = v0; acc[i][j][1] = v1;
            acc[i][j][2] = v2; acc[i][j][3] = v3;
            *(float2*)(Cb + (size_t)(gm0 + rl) * LL + col) = make_float2(v0, v1);
            *(float2*)(Cb + (size_t)(gm0 + rl + 8) * LL + col) = make_float2(v2, v3);
            vmax[i][0] = fmaxf(vmax[i][0], fmaxf(v0, v1));
            vmax[i][1] = fmaxf(vmax[i][1], fmaxf(v2, v3));
        }
    }
    // reduce max over tq quad (lanes xor 1, 2)
#pragma unroll
    for (int i = 0; i < 2; i++)
#pragma unroll
        for (int s = 0; s < 2; s++) {
            float m = vmax[i][s];
            m = fmaxf(m, __shfl_xor_sync(0xffffffffu, m, 1));
            m = fmaxf(m, __shfl_xor_sync(0xffffffffu, m, 2));
            vmax[i][s] = m;
        }
    if (tq == 0) {
#pragma unroll
        for (int i = 0; i < 2; i++) {
            sm[wn][mloc + i * 16 + gr] = vmax[i][0];
            sm[wn][mloc + i * 16 + gr + 8] = vmax[i][1];
        }
    }
    __syncthreads();
    // merged row max, then partial sumexp
#pragma unroll
    for (int i = 0; i < 2; i++) {
        const int r0 = mloc + i * 16 + gr, r1 = r0 + 8;
        const float M0 = fmaxf(sm[0][r0], sm[1][r0]);
        const float M1 = fmaxf(sm[0][r1], sm[1][r1]);
        float s0 = 0.f, s1 = 0.f;
#pragma unroll
        for (int j = 0; j < 8; j++) {
            s0 += __expf(acc[i][j][0] - M0) + __expf(acc[i][j][1] - M0);
            s1 += __expf(acc[i][j][2] - M1) + __expf(acc[i][j][3] - M1);
        }
        s0 += __shfl_xor_sync(0xffffffffu, s0, 1);
        s0 += __shfl_xor_sync(0xffffffffu, s0, 2);
        s1 += __shfl_xor_sync(0xffffffffu, s1, 1);
        s1 += __shfl_xor_sync(0xffffffffu, s1, 2);
        if (tq == 0) {
            sl[wn][r0] = s0;
            sl[wn][r1] = s1;
        }
    }
    __syncthreads();
    if (tid < 128) {
        const float M = fmaxf(sm[0][tid], sm[1][tid]);
        const float L = sl[0][tid] + sl[1][tid];
        const size_t o = (((size_t)z * LL + gm0 + tid) << 4) + blockIdx.x;
        g_stat_m[o] = M;
        g_stat_l[o] = L;
    }
}

// ---------------- fused: softmax-normalize S -> P (write) + ctx = P @ vt^T ----------------
__global__ __launch_bounds__(256) void k_ctx(float* __restrict__ attn) {
    const int z = blockIdx.z, b_ = z >> 4, h = z & 15;
    const int m0 = blockIdx.y * 128;
    const int tid = threadIdx.x;

    __shared__ float sM[128], sI[128];
    __shared__ float As[2][128 * 20];
    __shared__ float Bs[2][64 * 20];

    // reduce 16 per-tile stats -> (M, 1/L) per row
    if (tid < 128) {
        const size_t base = (((size_t)z * LL + m0 + tid) << 4);
        float m_[16], l_[16];
#pragma unroll
        for (int t = 0; t < 16; t += 4) {
            float4 a = *(const float4*)(g_stat_m + base + t);
            m_[t] = a.x; m_[t + 1] = a.y; m_[t + 2] = a.z; m_[t + 3] = a.w;
            float4 b = *(const float4*)(g_stat_l + base + t);
            l_[t] = b.x; l_[t + 1] = b.y; l_[t + 2] = b.z; l_[t + 3] = b.w;
        }
        float M = m_[0];
#pragma unroll
        for (int t = 1; t < 16; t++) M = fmaxf(M, m_[t]);
        float L = 0.f;
#pragma unroll
        for (int t = 0; t < 16; t++) L += l_[t] * __expf(m_[t] - M);
        sM[tid] = M;
        sI[tid] = 1.0f / L;
    }
    __syncthreads();

    float* A = attn + (size_t)z * LL * LL + (size_t)m0 * LL;
    const float* Bp = g_vt + (size_t)z * 64 * LL;

    const int lane = tid & 31, w = tid >> 5;
    const int m_base = (w & 3) * 32;
    const int n_base = (w >> 2) * 32;
    const int gr = lane >> 2, tq = lane & 3;

    // A rows handled by this thread (fixed across k): tid>>2 and tid>>2 + 64
    const int ar0 = tid >> 2, ar1 = ar0 + 64;
    const float M0 = sM[ar0], I0 = sI[ar0];
    const float M1 = sM[ar1], I1 = sI[ar1];
    const int ac = (tid & 3) << 2;

    float acc[2][4][4];
#pragma unroll
    for (int i = 0; i < 2; i++)
#pragma unroll
        for (int j = 0; j < 4; j++)
#pragma unroll
            for (int r = 0; r < 4; r++) acc[i][j][r] = 0.f;

    float4 ra[2], rb;

    // prologue k0 = 0: load S, transform to P, write P, stage to smem
    {
        float4 s0 = *(const float4*)(A + (size_t)ar0 * LL + ac);
        float4 s1 = *(const float4*)(A + (size_t)ar1 * LL + ac);
        ra[0] = make_float4(__expf(s0.x - M0) * I0, __expf(s0.y - M0) * I0,
                            __expf(s0.z - M0) * I0, __expf(s0.w - M0) * I0);
        ra[1] = make_float4(__expf(s1.x - M1) * I1, __expf(s1.y - M1) * I1,
                            __expf(s1.z - M1) * I1, __expf(s1.w - M1) * I1);
        *(float4*)(A + (size_t)ar0 * LL + ac) = ra[0];
        *(float4*)(A + (size_t)ar1 * LL + ac) = ra[1];
        rb = *(const float4*)(Bp + (size_t)(tid >> 2) * LL + ac);
        *(float4*)&As[0][ar0 * 20 + ac] = ra[0];
        *(float4*)&As[0][ar1 * 20 + ac] = ra[1];
        *(float4*)&Bs[0][(tid >> 2) * 20 + ac] = rb;
    }
    __syncthreads();

    const int S = LL >> 4;   // 128 stages
    for (int s = 0; s < S; s++) {
        const int cur = s & 1;
        if (s + 1 < S) {
            const int k0 = (s + 1) << 4;
            float4 s0 = *(const float4*)(A + (size_t)ar0 * LL + k0 + ac);
            float4 s1 = *(const float4*)(A + (size_t)ar1 * LL + k0 + ac);
            ra[0] = make_float4(__expf(s0.x - M0) * I0, __expf(s0.y - M0) * I0,
                                __expf(s0.z - M0) * I0, __expf(s0.w - M0) * I0);
            ra[1] = make_float4(__expf(s1.x - M1) * I1, __expf(s1.y - M1) * I1,
                                __expf(s1.z - M1) * I1, __expf(s1.w - M1) * I1);
            *(float4*)(A + (size_t)ar0 * LL + k0 + ac) = ra[0];
            *(float4*)(A + (size_t)ar1 * LL + k0 + ac) = ra[1];
            rb = *(const float4*)(Bp + (size_t)(tid >> 2) * LL + k0 + ac);
        }

#pragma unroll
        for (int kk = 0; kk < 16; kk += 8) {
            uint32_t af[2][4], bf[4][2];
#pragma unroll
            for (int i = 0; i < 2; i++) {
                const float* ap = &As[cur][(m_base + i * 16) * 20 + kk];
                af[i][0] = f2tf(ap[gr * 20 + tq]);
                af[i][1] = f2tf(ap[(gr + 8) * 20 + tq]);
                af[i][2] = f2tf(ap[gr * 20 + tq + 4]);
                af[i][3] = f2tf(ap[(gr + 8) * 20 + tq + 4]);
            }
#pragma unroll
            for (int j = 0; j < 4; j++) {
                const float* bp = &Bs[cur][(n_base + j * 8 + gr) * 20 + kk + tq];
                bf[j][0] = f2tf(bp[0]);
                bf[j][1] = f2tf(bp[4]);
            }
#pragma unroll
            for (int i = 0; i < 2; i++)
#pragma unroll
                for (int j = 0; j < 4; j++) mma8(acc[i][j], af[i], bf[j]);
        }

        if (s + 1 < S) {
            const int nxt = cur ^ 1;
            *(float4*)&As[nxt][ar0 * 20 + ac] = ra[0];
            *(float4*)&As[nxt][ar1 * 20 + ac] = ra[1];
            *(float4*)&Bs[nxt][(tid >> 2) * 20 + ac] = rb;
        }
        __syncthreads();
    }

    // epilogue: ctx
    const int mw0 = m0 + m_base;
#pragma unroll
    for (int i = 0; i < 2; i++) {
        const int r0 = mw0 + i * 16 + gr;
#pragma unroll
        for (int j = 0; j < 4; j++) {
            const int col = n_base + j * 8 + tq * 2;
            *(float2*)(g_ctx + (size_t)(b_ * LL + r0) * DD + h * 64 + col) =
                make_float2(acc[i][j][0], acc[i][j][1]);
            *(float2*)(g_ctx + (size_t)(b_ * LL + r0 + 8) * DD + h * 64 + col) =
                make_float2(acc[i][j][2], acc[i][j][3]);
        }
    }
}

// ---------------- dense: g_tmp = ctx @ W^T + b + resid ----------------
__global__ __launch_bounds__(256) void k_dense(const float* __restrict__ W,
                                               const float* __restrict__ bias,
                                               const float* __restrict__ resid) {
    float acc[2][8][4];
    const float* A = g_ctx + (size_t)blockIdx.y * 128 * DD;
    const float* Bp = W + (size_t)blockIdx.x * 128 * DD;
    gemm_tc<128>(A, DD, Bp, DD, DD, acc);

    const int lane = threadIdx.x & 31, w = threadIdx.x >> 5;
    const int m0 = blockIdx.y * 128 + (w & 3) * 32;
    const int n0 = blockIdx.x * 128 + (w >> 2) * 64;
    const int gr = lane >> 2, tq = lane & 3;
#pragma unroll
    for (int i = 0; i < 2; i++) {
        const int r0 = m0 + i * 16 + gr;
#pragma unroll
        for (int j = 0; j < 8; j++) {
            const int col = n0 + j * 8 + tq * 2;
            const float b0 = bias[col], b1 = bias[col + 1];
            const float* R0 = resid + (size_t)r0 * DD + col;
            const float* R1 = resid + (size_t)(r0 + 8) * DD + col;
            *(float2*)(g_tmp + (size_t)r0 * DD + col) =
                make_float2(acc[i][j][0] + b0 + R0[0], acc[i][j][1] + b1 + R0[1]);
            *(float2*)(g_tmp + (size_t)(r0 + 8) * DD + col) =
                make_float2(acc[i][j][2] + b0 + R1[0], acc[i][j][3] + b1 + R1[1]);
        }
    }
}

// ---------------- LayerNorm ----------------
__global__ __launch_bounds__(256) void ln_kernel(
    const float* __restrict__ lnw, const float* __restrict__ lnb,
    float* __restrict__ out) {
    const int row = blockIdx.x;
    const int tid = threadIdx.x;
    const float4* x4 = (const float4*)(g_tmp + (size_t)row * DD);
    float4 x = x4[tid];

    __shared__ float sred[8];
    const int wid = tid >> 5, lid = tid & 31;

    float lsum = x.x + x.y + x.z + x.w;
#pragma unroll
    for (int off = 16; off; off >>= 1) lsum += __shfl_xor_sync(0xffffffffu, lsum, off);
    if (lid == 0) sred[wid] = lsum;
    __syncthreads();
    float tot = 0.f;
#pragma unroll
    for (int i = 0; i < 8; i++) tot += sred[i];
    float mu = tot * (1.0f / DD);

    float d0 = x.x - mu, d1 = x.y - mu, d2 = x.z - mu, d3 = x.w - mu;
    float lsq = d0 * d0 + d1 * d1 + d2 * d2 + d3 * d3;
    __syncthreads();
#pragma unroll
    for (int off = 16; off; off >>= 1) lsq += __shfl_xor_sync(0xffffffffu, lsq, off);
    if (lid == 0) sred[wid] = lsq;
    __syncthreads();
    float tot2 = 0.f;
#pragma unroll
    for (int i = 0; i < 8; i++) tot2 += sred[i];
    float var = tot2 * (1.0f / DD);
    float sc = rsqrtf(var + EPSV);

    const float4 w = ((const float4*)lnw)[tid];
    const float4 b = ((const float4*)lnb)[tid];
    float4 o = make_float4(d0 * sc * w.x + b.x, d1 * sc * w.y + b.y,
                           d2 * sc * w.z + b.z, d3 * sc * w.w + b.w);
    ((float4*)(out + (size_t)row * DD))[tid] = o;
}

// =====================================================================
extern "C" void kernel_launch(void* const* d_in, const int* in_sizes, int n_in,
                              void* d_out, int out_size) {
    const float* q    = (const float*)d_in[0];
    const float* k    = (const float*)d_in[1];
    const float* v    = (const float*)d_in[2];
    const int*   mask = (const int*)d_in[3];
    const float* wq_w = (const float*)d_in[4];
    const float* wq_b = (const float*)d_in[5];
    const float* wk_w = (const float*)d_in[6];
    const float* wk_b = (const float*)d_in[7];
    const float* wv_w = (const float*)d_in[8];
    const float* wv_b = (const float*)d_in[9];
    const float* dw   = (const float*)d_in[10];
    const float* db   = (const float*)d_in[11];
    const float* lnw  = (const float*)d_in[12];
    const float* lnb  = (const float*)d_in[13];

    float* out0 = (float*)d_out;
    float* attn = out0 + (size_t)BB * LL * DD;   // tuple order: (out, attn_weights)

    k_proj<<<dim3(8, 32), 256>>>(q, wq_w, wq_b, 0.125f, 0);
    k_proj<<<dim3(8, 32), 256>>>(k, wk_w, wk_b, 1.0f, 1);
    k_proj<<<dim3(8, 32), 256>>>(v, wv_w, wv_b, 1.0f, 2);
    k_trans<<<dim3(64, 2, 32), dim3(32, 8)>>>();
    k_score<<<dim3(16, 16, 32), 256>>>(attn, mask);
    k_ctx<<<dim3(1, 16, 32), 256>>>(attn);
    k_dense<<<dim3(8, 32), 256>>>(dw, db, q);
    ln_kernel<<<BB * LL, 256>>>(lnw, lnb, out0);
}

// round 7
// speedup vs baseline: 1.0037x; 1.0037x over previous
#include <cuda_runtime.h>
#include <cstdint>

#define BB 2
#define LL 2048
#define DD 1024
#define HH 16
#define NEGV (-1000000000.0f)
#define EPSV 1e-6f

// ---------------- scratch (no allocations allowed) ----------------
__device__ float g_q4[(size_t)BB * LL * DD];       // Q proj, pre-scaled by 1/8
__device__ float g_k4[(size_t)BB * LL * DD];       // K proj
__device__ float g_vt[(size_t)BB * HH * 64 * LL];  // V proj transposed [b][h][d][l]
__device__ float g_ctx[(size_t)BB * LL * DD];      // ctx
__device__ float g_tmp[(size_t)BB * LL * DD];      // V natural, then pre-LN
__device__ float g_stat_m[(size_t)BB * HH * LL * 16];  // per (row, ktile) max
__device__ float g_stat_l[(size_t)BB * HH * LL * 16];  // per (row, ktile) sumexp
__device__ float g_rowM[(size_t)BB * HH * LL];         // per-row max
__device__ float g_rowI[(size_t)BB * HH * LL];         // per-row 1/sumexp

// ---------------- tf32 helpers ----------------
__device__ __forceinline__ uint32_t f2tf(float f) {
    uint32_t u;
    asm("cvt.rna.tf32.f32 %0, %1;" : "=r"(u) : "f"(f));
    return u;
}

__device__ __forceinline__ void mma8(float* c, const uint32_t* a, const uint32_t* b) {
    asm volatile(
        "mma.sync.aligned.m16n8k8.row.col.f32.tf32.tf32.f32 "
        "{%0,%1,%2,%3}, {%4,%5,%6,%7}, {%8,%9}, {%0,%1,%2,%3};"
        : "+f"(c[0]), "+f"(c[1]), "+f"(c[2]), "+f"(c[3])
        : "r"(a[0]), "r"(a[1]), "r"(a[2]), "r"(a[3]), "r"(b[0]), "r"(b[1]));
}

// =====================================================================
// NT GEMM core: C[128 x NROWS] += A[128 x K] * B[NROWS x K]^T
// 256 threads, 8 warps (4 M x 2 N), warp tile 32 x NROWS/2.
// BK=16, double-buffered smem, row pad to 20 floats.
// =====================================================================
template <int NROWS>
__device__ __forceinline__ void gemm_tc(const float* __restrict__ A, int lda,
                                        const float* __restrict__ B, int ldb,
                                        int K, float acc[2][NROWS / 16][4]) {
    constexpr int NT = NROWS / 16;
    constexpr int BT = NROWS / 64;
    __shared__ float As[2][128 * 20];
    __shared__ float Bs[2][NROWS * 20];

    const int tid = threadIdx.x;
    const int lane = tid & 31, w = tid >> 5;
    const int m_base = (w & 3) * 32;
    const int n_base = (w >> 2) * (NROWS / 2);
    const int gr = lane >> 2, tq = lane & 3;

#pragma unroll
    for (int i = 0; i < 2; i++)
#pragma unroll
        for (int j = 0; j < NT; j++)
#pragma unroll
            for (int r = 0; r < 4; r++) acc[i][j][r] = 0.f;

    const int S = K >> 4;
    float4 ra[2], rb[BT];

#pragma unroll
    for (int t = 0; t < 2; t++) {
        int idx = tid + t * 256;
        ra[t] = *(const float4*)(A + (size_t)(idx >> 2) * lda + ((idx & 3) << 2));
    }
#pragma unroll
    for (int t = 0; t < BT; t++) {
        int idx = tid + t * 256;
        rb[t] = *(const float4*)(B + (size_t)(idx >> 2) * ldb + ((idx & 3) << 2));
    }
#pragma unroll
    for (int t = 0; t < 2; t++) {
        int idx = tid + t * 256;
        *(float4*)&As[0][(idx >> 2) * 20 + ((idx & 3) << 2)] = ra[t];
    }
#pragma unroll
    for (int t = 0; t < BT; t++) {
        int idx = tid + t * 256;
        *(float4*)&Bs[0][(idx >> 2) * 20 + ((idx & 3) << 2)] = rb[t];
    }
    __syncthreads();

    for (int s = 0; s < S; s++) {
        const int cur = s & 1;
        if (s + 1 < S) {
            const int k0 = (s + 1) << 4;
#pragma unroll
            for (int t = 0; t < 2; t++) {
                int idx = tid + t * 256;
                ra[t] = *(const float4*)(A + (size_t)(idx >> 2) * lda + k0 + ((idx & 3) << 2));
            }
#pragma unroll
            for (int t = 0; t < BT; t++) {
                int idx = tid + t * 256;
                rb[t] = *(const float4*)(B + (size_t)(idx >> 2) * ldb + k0 + ((idx & 3) << 2));
            }
        }

#pragma unroll
        for (int kk = 0; kk < 16; kk += 8) {
            uint32_t af[2][4], bf[NT][2];
#pragma unroll
            for (int i = 0; i < 2; i++) {
                const float* ap = &As[cur][(m_base + i * 16) * 20 + kk];
                af[i][0] = f2tf(ap[gr * 20 + tq]);
                af[i][1] = f2tf(ap[(gr + 8) * 20 + tq]);
                af[i][2] = f2tf(ap[gr * 20 + tq + 4]);
                af[i][3] = f2tf(ap[(gr + 8) * 20 + tq + 4]);
            }
#pragma unroll
            for (int j = 0; j < NT; j++) {
                const float* bp = &Bs[cur][(n_base + j * 8 + gr) * 20 + kk + tq];
                bf[j][0] = f2tf(bp[0]);
                bf[j][1] = f2tf(bp[4]);
            }
#pragma unroll
            for (int i = 0; i < 2; i++)
#pragma unroll
                for (int j = 0; j < NT; j++) mma8(acc[i][j], af[i], bf[j]);
        }

        if (s + 1 < S) {
            const int nxt = cur ^ 1;
#pragma unroll
            for (int t = 0; t < 2; t++) {
                int idx = tid + t * 256;
                *(float4*)&As[nxt][(idx >> 2) * 20 + ((idx & 3) << 2)] = ra[t];
            }
#pragma unroll
            for (int t = 0; t < BT; t++) {
                int idx = tid + t * 256;
                *(float4*)&Bs[nxt][(idx >> 2) * 20 + ((idx & 3) << 2)] = rb[t];
            }
        }
        __syncthreads();
    }
}

// ---------------- projection: out = X @ W^T + b (times scale) ----------------
__global__ __launch_bounds__(256) void k_proj(const float* __restrict__ X,
                                              const float* __restrict__ W,
                                              const float* __restrict__ bias,
                                              float scale, int sel) {
    float acc[2][8][4];
    const float* A = X + (size_t)blockIdx.y * 128 * DD;
    const float* Bp = W + (size_t)blockIdx.x * 128 * DD;
    gemm_tc<128>(A, DD, Bp, DD, DD, acc);

    float* out = (sel == 0) ? g_q4 : (sel == 1) ? g_k4 : g_tmp;
    const int lane = threadIdx.x & 31, w = threadIdx.x >> 5;
    const int m0 = blockIdx.y * 128 + (w & 3) * 32;
    const int n0 = blockIdx.x * 128 + (w >> 2) * 64;
    const int gr = lane >> 2, tq = lane & 3;
#pragma unroll
    for (int i = 0; i < 2; i++) {
        const int r0 = m0 + i * 16 + gr;
#pragma unroll
        for (int j = 0; j < 8; j++) {
            const int col = n0 + j * 8 + tq * 2;
            const float b0 = bias[col], b1 = bias[col + 1];
            *(float2*)(out + (size_t)r0 * DD + col) =
                make_float2((acc[i][j][0] + b0) * scale, (acc[i][j][1] + b1) * scale);
            *(float2*)(out + (size_t)(r0 + 8) * DD + col) =
                make_float2((acc[i][j][2] + b0) * scale, (acc[i][j][3] + b1) * scale);
        }
    }
}

// ---------------- transpose V: g_tmp -> g_vt [b][h][d][l] ----------------
__global__ __launch_bounds__(256) void k_trans() {
    __shared__ float t[32][33];
    const int b = blockIdx.z >> 4, h = blockIdx.z & 15;
    const int l0 = blockIdx.x * 32, d0 = blockIdx.y * 32;
    for (int i = threadIdx.y; i < 32; i += 8)
        t[i][threadIdx.x] =
            g_tmp[(size_t)(b * LL + l0 + i) * DD + h * 64 + d0 + threadIdx.x];
    __syncthreads();
    for (int i = threadIdx.y; i < 32; i += 8)
        g_vt[((size_t)((b * HH + h) * 64) + d0 + i) * LL + l0 + threadIdx.x] =
            t[threadIdx.x][i];
}

// ---------------- scores + mask + per-tile softmax stats ----------------
__global__ __launch_bounds__(256) void k_score(float* __restrict__ attn,
                                               const int* __restrict__ mask) {
    float acc[2][8][4];
    const int z = blockIdx.z, b_ = z >> 4, h = z & 15;
    const float* A = g_q4 + (size_t)b_ * LL * DD + h * 64 + (size_t)blockIdx.y * 128 * DD;
    const float* Bp = g_k4 + (size_t)b_ * LL * DD + h * 64 + (size_t)blockIdx.x * 128 * DD;
    gemm_tc<128>(A, DD, Bp, DD, 64, acc);

    __shared__ float sm[2][128], sl[2][128];

    float* Cb = attn + (size_t)z * LL * LL;
    const int tid = threadIdx.x;
    const int lane = tid & 31, w = tid >> 5;
    const int wn = w >> 2;
    const int mloc = (w & 3) * 32;
    const int gm0 = blockIdx.y * 128;
    const int n0 = blockIdx.x * 128 + wn * 64;
    const int gr = lane >> 2, tq = lane & 3;

    float vmax[2][2] = {{-3.4e38f, -3.4e38f}, {-3.4e38f, -3.4e38f}};
#pragma unroll
    for (int i = 0; i < 2; i++) {
        const int rl = mloc + i * 16 + gr;
        const size_t mrow0 = ((size_t)b_ * LL + gm0 + rl) * LL;
        const size_t mrow1 = ((size_t)b_ * LL + gm0 + rl + 8) * LL;
#pragma unroll
        for (int j = 0; j < 8; j++) {
            const int col = n0 + j * 8 + tq * 2;
            int2 k0 = *(const int2*)(mask + mrow0 + col);
            int2 k1 = *(const int2*)(mask + mrow1 + col);
            float v0 = (k0.x == 0) ? NEGV : acc[i][j][0];
            float v1 = (k0.y == 0) ? NEGV : acc[i][j][1];
            float v2 = (k1.x == 0) ? NEGV : acc[i][j][2];
            float v3 = (k1.y == 0) ? NEGV : acc[i][j][3];
            acc[i][j][0] = v0; acc[i][j][1] = v1;
            acc[i][j][2] = v2; acc[i][j][3] = v3;
            *(float2*)(Cb + (size_t)(gm0 + rl) * LL + col) = make_float2(v0, v1);
            *(float2*)(Cb + (size_t)(gm0 + rl + 8) * LL + col) = make_float2(v2, v3);
            vmax[i][0] = fmaxf(vmax[i][0], fmaxf(v0, v1));
            vmax[i][1] = fmaxf(vmax[i][1], fmaxf(v2, v3));
        }
    }
#pragma unroll
    for (int i = 0; i < 2; i++)
#pragma unroll
        for (int s = 0; s < 2; s++) {
            float m = vmax[i][s];
            m = fmaxf(m, __shfl_xor_sync(0xffffffffu, m, 1));
            m = fmaxf(m, __shfl_xor_sync(0xffffffffu, m, 2));
            vmax[i][s] = m;
        }
    if (tq == 0) {
#pragma unroll
        for (int i = 0; i < 2; i++) {
            sm[wn][mloc + i * 16 + gr] = vmax[i][0];
            sm[wn][mloc + i * 16 + gr + 8] = vmax[i][1];
        }
    }
    __syncthreads();
#pragma unroll
    for (int i = 0; i < 2; i++) {
        const int r0 = mloc + i * 16 + gr, r1 = r0 + 8;
        const float M0 = fmaxf(sm[0][r0], sm[1][r0]);
        const float M1 = fmaxf(sm[0][r1], sm[1][r1]);
        float s0 = 0.f, s1 = 0.f;
#pragma unroll
        for (int j = 0; j < 8; j++) {
            s0 += __expf(acc[i][j][0] - M0) + __expf(acc[i][j][1] - M0);
            s1 += __expf(acc[i][j][2] - M1) + __expf(acc[i][j][3] - M1);
        }
        s0 += __shfl_xor_sync(0xffffffffu, s0, 1);
        s0 += __shfl_xor_sync(0xffffffffu, s0, 2);
        s1 += __shfl_xor_sync(0xffffffffu, s1, 1);
        s1 += __shfl_xor_sync(0xffffffffu, s1, 2);
        if (tq == 0) {
            sl[wn][r0] = s0;
            sl[wn][r1] = s1;
        }
    }
    __syncthreads();
    if (tid < 128) {
        const float M = fmaxf(sm[0][tid], sm[1][tid]);
        const float L = sl[0][tid] + sl[1][tid];
        const size_t o = (((size_t)z * LL + gm0 + tid) << 4) + blockIdx.x;
        g_stat_m[o] = M;
        g_stat_l[o] = L;
    }
}

// ---------------- fold 16 per-tile stats -> per-row (M, 1/L) ----------------
__global__ __launch_bounds__(256) void k_rowstats() {
    const int row = blockIdx.x * 256 + threadIdx.x;   // 65536 rows
    const size_t base = (size_t)row << 4;
    float m_[16], l_[16];
#pragma unroll
    for (int t = 0; t < 16; t += 4) {
        float4 a = *(const float4*)(g_stat_m + base + t);
        m_[t] = a.x; m_[t + 1] = a.y; m_[t + 2] = a.z; m_[t + 3] = a.w;
        float4 b = *(const float4*)(g_stat_l + base + t);
        l_[t] = b.x; l_[t + 1] = b.y; l_[t + 2] = b.z; l_[t + 3] = b.w;
    }
    float M = m_[0];
#pragma unroll
    for (int t = 1; t < 16; t++) M = fmaxf(M, m_[t]);
    float L = 0.f;
#pragma unroll
    for (int t = 0; t < 16; t++) L += l_[t] * __expf(m_[t] - M);
    g_rowM[row] = M;
    g_rowI[row] = 1.0f / L;
}

// ---------------- normalize: P = exp(S - M) * I, pure stream ----------------
__global__ __launch_bounds__(256) void k_norm(float* __restrict__ attn) {
    float4* a4 = (float4*)attn;
#pragma unroll
    for (int t = 0; t < 2; t++) {
        const size_t i = (size_t)blockIdx.x * 512 + t * 256 + threadIdx.x;
        const int row = (int)(i >> 9);              // 512 float4 per row
        const float M = g_rowM[row];
        const float I = g_rowI[row];
        float4 s = a4[i];
        a4[i] = make_float4(__expf(s.x - M) * I, __expf(s.y - M) * I,
                            __expf(s.z - M) * I, __expf(s.w - M) * I);
    }
}

// ---------------- ctx: g_ctx = P[z] @ vt[z]^T ----------------
__global__ __launch_bounds__(256) void k_ctx(const float* __restrict__ attn) {
    float acc[2][4][4];
    const int z = blockIdx.z, b_ = z >> 4, h = z & 15;
    const float* A = attn + (size_t)z * LL * LL + (size_t)blockIdx.y * 128 * LL;
    const float* Bp = g_vt + (size_t)z * 64 * LL;
    gemm_tc<64>(A, LL, Bp, LL, LL, acc);

    const int lane = threadIdx.x & 31, w = threadIdx.x >> 5;
    const int m0 = blockIdx.y * 128 + (w & 3) * 32;
    const int n0 = (w >> 2) * 32;
    const int gr = lane >> 2, tq = lane & 3;
#pragma unroll
    for (int i = 0; i < 2; i++) {
        const int r0 = m0 + i * 16 + gr;
#pragma unroll
        for (int j = 0; j < 4; j++) {
            const int col = n0 + j * 8 + tq * 2;
            *(float2*)(g_ctx + (size_t)(b_ * LL + r0) * DD + h * 64 + col) =
                make_float2(acc[i][j][0], acc[i][j][1]);
            *(float2*)(g_ctx + (size_t)(b_ * LL + r0 + 8) * DD + h * 64 + col) =
                make_float2(acc[i][j][2], acc[i][j][3]);
        }
    }
}

// ---------------- dense: g_tmp = ctx @ W^T + b + resid ----------------
__global__ __launch_bounds__(256) void k_dense(const float* __restrict__ W,
                                               const float* __restrict__ bias,
                                               const float* __restrict__ resid) {
    float acc[2][8][4];
    const float* A = g_ctx + (size_t)blockIdx.y * 128 * DD;
    const float* Bp = W + (size_t)blockIdx.x * 128 * DD;
    gemm_tc<128>(A, DD, Bp, DD, DD, acc);

    const int lane = threadIdx.x & 31, w = threadIdx.x >> 5;
    const int m0 = blockIdx.y * 128 + (w & 3) * 32;
    const int n0 = blockIdx.x * 128 + (w >> 2) * 64;
    const int gr = lane >> 2, tq = lane & 3;
#pragma unroll
    for (int i = 0; i < 2; i++) {
        const int r0 = m0 + i * 16 + gr;
#pragma unroll
        for (int j = 0; j < 8; j++) {
            const int col = n0 + j * 8 + tq * 2;
            const float b0 = bias[col], b1 = bias[col + 1];
            const float* R0 = resid + (size_t)r0 * DD + col;
            const float* R1 = resid + (size_t)(r0 + 8) * DD + col;
            *(float2*)(g_tmp + (size_t)r0 * DD + col) =
                make_float2(acc[i][j][0] + b0 + R0[0], acc[i][j][1] + b1 + R0[1]);
            *(float2*)(g_tmp + (size_t)(r0 + 8) * DD + col) =
                make_float2(acc[i][j][2] + b0 + R1[0], acc[i][j][3] + b1 + R1[1]);
        }
    }
}

// ---------------- LayerNorm ----------------
__global__ __launch_bounds__(256) void ln_kernel(
    const float* __restrict__ lnw, const float* __restrict__ lnb,
    float* __restrict__ out) {
    const int row = blockIdx.x;
    const int tid = threadIdx.x;
    const float4* x4 = (const float4*)(g_tmp + (size_t)row * DD);
    float4 x = x4[tid];

    __shared__ float sred[8];
    const int wid = tid >> 5, lid = tid & 31;

    float lsum = x.x + x.y + x.z + x.w;
#pragma unroll
    for (int off = 16; off; off >>= 1) lsum += __shfl_xor_sync(0xffffffffu, lsum, off);
    if (lid == 0) sred[wid] = lsum;
    __syncthreads();
    float tot = 0.f;
#pragma unroll
    for (int i = 0; i < 8; i++) tot += sred[i];
    float mu = tot * (1.0f / DD);

    float d0 = x.x - mu, d1 = x.y - mu, d2 = x.z - mu, d3 = x.w - mu;
    float lsq = d0 * d0 + d1 * d1 + d2 * d2 + d3 * d3;
    __syncthreads();
#pragma unroll
    for (int off = 16; off; off >>= 1) lsq += __shfl_xor_sync(0xffffffffu, lsq, off);
    if (lid == 0) sred[wid] = lsq;
    __syncthreads();
    float tot2 = 0.f;
#pragma unroll
    for (int i = 0; i < 8; i++) tot2 += sred[i];
    float var = tot2 * (1.0f / DD);
    float sc = rsqrtf(var + EPSV);

    const float4 w = ((const float4*)lnw)[tid];
    const float4 b = ((const float4*)lnb)[tid];
    float4 o = make_float4(d0 * sc * w.x + b.x, d1 * sc * w.y + b.y,
                           d2 * sc * w.z + b.z, d3 * sc * w.w + b.w);
    ((float4*)(out + (size_t)row * DD))[tid] = o;
}

// =====================================================================
extern "C" void kernel_launch(void* const* d_in, const int* in_sizes, int n_in,
                              void* d_out, int out_size) {
    const float* q    = (const float*)d_in[0];
    const float* k    = (const float*)d_in[1];
    const float* v    = (const float*)d_in[2];
    const int*   mask = (const int*)d_in[3];
    const float* wq_w = (const float*)d_in[4];
    const float* wq_b = (const float*)d_in[5];
    const float* wk_w = (const float*)d_in[6];
    const float* wk_b = (const float*)d_in[7];
    const float* wv_w = (const float*)d_in[8];
    const float* wv_b = (const float*)d_in[9];
    const float* dw   = (const float*)d_in[10];
    const float* db   = (const float*)d_in[11];
    const float* lnw  = (const float*)d_in[12];
    const float* lnb  = (const float*)d_in[13];

    float* out0 = (float*)d_out;
    float* attn = out0 + (size_t)BB * LL * DD;   // tuple order: (out, attn_weights)

    k_proj<<<dim3(8, 32), 256>>>(q, wq_w, wq_b, 0.125f, 0);
    k_proj<<<dim3(8, 32), 256>>>(k, wk_w, wk_b, 1.0f, 1);
    k_proj<<<dim3(8, 32), 256>>>(v, wv_w, wv_b, 1.0f, 2);
    k_trans<<<dim3(64, 2, 32), dim3(32, 8)>>>();
    k_score<<<dim3(16, 16, 32), 256>>>(attn, mask);
    k_rowstats<<<256, 256>>>();
    k_norm<<<65536, 256>>>(attn);
    k_ctx<<<dim3(1, 16, 32), 256>>>(attn);
    k_dense<<<dim3(8, 32), 256>>>(dw, db, q);
    ln_kernel<<<BB * LL, 256>>>(lnw, lnb, out0);
}